// round 1
// baseline (speedup 1.0000x reference)
#include <cuda_runtime.h>
#include <cstdint>

#define H 128
#define MAXN 100000

// Scratch (allocation-free rule: __device__ globals)
__device__ float g_x[MAXN * H];
__device__ float g_agg[MAXN * H];
__device__ float g_u[MAXN * H];

// ---------------------------------------------------------------------------
// x[i] = emb[z[i]]  (one float4 per thread)
// ---------------------------------------------------------------------------
__global__ void embed_kernel(const float* __restrict__ emb,
                             const int* __restrict__ z,
                             float* __restrict__ x, int N)
{
    int i = blockIdx.x * blockDim.x + threadIdx.x;   // over N*32 float4s
    if (i >= N * (H / 4)) return;
    int row = i >> 5;
    int c   = i & 31;
    ((float4*)x)[i] = ((const float4*)(emb + (size_t)z[row] * H))[c];
}

// ---------------------------------------------------------------------------
// agg = x   (init for h = x + sum(messages))
// ---------------------------------------------------------------------------
__global__ void copy_kernel(float4* __restrict__ dst,
                            const float4* __restrict__ src, int n4)
{
    int i = blockIdx.x * blockDim.x + threadIdx.x;
    if (i < n4) dst[i] = src[i];
}

// ---------------------------------------------------------------------------
// Edge messages: one warp per edge, lane handles 4 channels.
//   proj = edge_attr[e] @ We + be        (We rows held in registers)
//   m    = relu(x[src] + proj)
//   agg[dst] += m                        (vector float4 atomic -> RED.128)
// ---------------------------------------------------------------------------
__global__ void edge_kernel(const float* __restrict__ x,
                            float* __restrict__ agg,
                            const int* __restrict__ src,
                            const int* __restrict__ dst,
                            const float* __restrict__ ea,
                            const float* __restrict__ We,
                            const float* __restrict__ be,
                            int E)
{
    const int lane = threadIdx.x & 31;
    const int c = lane * 4;
    const int warp = (blockIdx.x * blockDim.x + threadIdx.x) >> 5;
    const int nwarps = (gridDim.x * blockDim.x) >> 5;

    // Per-thread slice of We (4 x H) and be, loaded once.
    const float4 w0 = *(const float4*)(We + 0 * H + c);
    const float4 w1 = *(const float4*)(We + 1 * H + c);
    const float4 w2 = *(const float4*)(We + 2 * H + c);
    const float4 w3 = *(const float4*)(We + 3 * H + c);
    const float4 bb = *(const float4*)(be + c);

    for (int e = warp; e < E; e += nwarps) {
        int s = __ldg(src + e);
        int d = __ldg(dst + e);
        float4 a = *(const float4*)(ea + 4 * (size_t)e);

        float4 p;
        p.x = bb.x + a.x * w0.x + a.y * w1.x + a.z * w2.x + a.w * w3.x;
        p.y = bb.y + a.x * w0.y + a.y * w1.y + a.z * w2.y + a.w * w3.y;
        p.z = bb.z + a.x * w0.z + a.y * w1.z + a.z * w2.z + a.w * w3.z;
        p.w = bb.w + a.x * w0.w + a.y * w1.w + a.z * w2.w + a.w * w3.w;

        float4 xv = *(const float4*)(x + (size_t)s * H + c);
        float4 m;
        m.x = fmaxf(xv.x + p.x, 0.0f);
        m.y = fmaxf(xv.y + p.y, 0.0f);
        m.z = fmaxf(xv.z + p.z, 0.0f);
        m.w = fmaxf(xv.w + p.w, 0.0f);

        atomicAdd((float4*)(agg + (size_t)d * H + c), m);
    }
}

// ---------------------------------------------------------------------------
// C[M,128] = act(A[M,128] @ B[128,128] + bias)
// BM=64, full N and K resident in smem (96 KB dynamic), 256 threads,
// each thread computes an 8x4 microtile. A-operand reads are warp-broadcast
// from smem (all lanes of a warp share ty).
// ---------------------------------------------------------------------------
__global__ __launch_bounds__(256) void gemm_kernel(
    const float* __restrict__ A, const float* __restrict__ B,
    const float* __restrict__ bias, float* __restrict__ C,
    int M, int do_silu)
{
    extern __shared__ float sm[];
    float* As = sm;              // 64 * 128
    float* Bs = sm + 64 * H;     // 128 * 128

    const int t = threadIdx.x;
    const int row0 = blockIdx.x * 64;

    // Stage B (128x128) : 4096 float4, 16 per thread
    {
        const float4* B4 = (const float4*)B;
        float4* Bs4 = (float4*)Bs;
        #pragma unroll
        for (int i = 0; i < 16; i++) Bs4[t + 256 * i] = B4[t + 256 * i];
    }
    // Stage A tile (guarded for partial last block)
    {
        int rows = M - row0; if (rows > 64) rows = 64;
        const float4* A4 = (const float4*)(A + (size_t)row0 * H);
        float4* As4 = (float4*)As;
        for (int i = t; i < rows * 32; i += 256) As4[i] = A4[i];
    }
    __syncthreads();

    const int tx = t & 31;       // column group
    const int ty = t >> 5;       // row group (uniform within warp)
    const int col = tx * 4;

    float acc[8][4];
    #pragma unroll
    for (int r = 0; r < 8; r++) { acc[r][0] = acc[r][1] = acc[r][2] = acc[r][3] = 0.0f; }

    #pragma unroll 8
    for (int k = 0; k < H; k++) {
        float4 b = *(const float4*)(Bs + k * H + col);
        #pragma unroll
        for (int r = 0; r < 8; r++) {
            float a = As[(ty * 8 + r) * H + k];   // warp-broadcast LDS
            acc[r][0] = fmaf(a, b.x, acc[r][0]);
            acc[r][1] = fmaf(a, b.y, acc[r][1]);
            acc[r][2] = fmaf(a, b.z, acc[r][2]);
            acc[r][3] = fmaf(a, b.w, acc[r][3]);
        }
    }

    const float4 bv = *(const float4*)(bias + col);
    #pragma unroll
    for (int r = 0; r < 8; r++) {
        int row = row0 + ty * 8 + r;
        if (row < M) {
            float4 v;
            v.x = acc[r][0] + bv.x;
            v.y = acc[r][1] + bv.y;
            v.z = acc[r][2] + bv.z;
            v.w = acc[r][3] + bv.w;
            if (do_silu) {
                v.x = v.x / (1.0f + __expf(-v.x));
                v.y = v.y / (1.0f + __expf(-v.y));
                v.z = v.z / (1.0f + __expf(-v.z));
                v.w = v.w / (1.0f + __expf(-v.w));
            }
            *(float4*)(C + (size_t)row * H + col) = v;
        }
    }
}

// ---------------------------------------------------------------------------
// batch_vec -> float tail of the output
// ---------------------------------------------------------------------------
__global__ void batch_kernel(const int* __restrict__ b, float* __restrict__ o, int N)
{
    int i = blockIdx.x * blockDim.x + threadIdx.x;
    if (i < N) o[i] = (float)b[i];
}

// ---------------------------------------------------------------------------
extern "C" void kernel_launch(void* const* d_in, const int* in_sizes, int n_in,
                              void* d_out, int out_size)
{
    const float* emb  = (const float*)d_in[0];
    const float* We   = (const float*)d_in[1];
    const float* be   = (const float*)d_in[2];
    const float* W1   = (const float*)d_in[3];
    const float* b1   = (const float*)d_in[4];
    const float* W2   = (const float*)d_in[5];
    const float* b2   = (const float*)d_in[6];
    const float* ea   = (const float*)d_in[7];
    const int*   z    = (const int*)d_in[8];
    const int*   ei   = (const int*)d_in[9];
    const int*   bat  = (const int*)d_in[10];

    const int N = in_sizes[8];
    const int E = in_sizes[9] / 2;
    float* out = (float*)d_out;

    float *x, *agg, *u;
    cudaGetSymbolAddress((void**)&x,   g_x);
    cudaGetSymbolAddress((void**)&agg, g_agg);
    cudaGetSymbolAddress((void**)&u,   g_u);

    const size_t gemm_smem = (64 * H + H * H) * sizeof(float);   // 96 KB
    cudaFuncSetAttribute(gemm_kernel, cudaFuncAttributeMaxDynamicSharedMemorySize,
                         (int)gemm_smem);

    embed_kernel<<<(N * (H / 4) + 255) / 256, 256>>>(emb, z, x, N);

    const int n4 = N * (H / 4);
    const int gemm_grid = (N + 63) / 64;

    for (int l = 0; l < 3; l++) {
        copy_kernel<<<(n4 + 255) / 256, 256>>>((float4*)agg, (const float4*)x, n4);
        edge_kernel<<<1184, 256>>>(x, agg, ei, ei + E, ea,
                                   We + (size_t)l * 4 * H, be + (size_t)l * H, E);
        gemm_kernel<<<gemm_grid, 256, gemm_smem>>>(
            agg, W1 + (size_t)l * H * H, b1 + (size_t)l * H, u, N, 1);
        float* dstp = (l == 2) ? out : x;
        gemm_kernel<<<gemm_grid, 256, gemm_smem>>>(
            u, W2 + (size_t)l * H * H, b2 + (size_t)l * H, dstp, N, 0);
    }

    if ((size_t)out_size >= (size_t)N * H + (size_t)N) {
        batch_kernel<<<(N + 255) / 256, 256>>>(bat, out + (size_t)N * H, N);
    }
}

// round 5
// speedup vs baseline: 1.1835x; 1.1835x over previous
#include <cuda_runtime.h>
#include <cuda_bf16.h>
#include <cstdint>

#define H 128
#define MAXN 100000

// ---------------------------------------------------------------------------
// Scratch (__device__ globals; no allocation allowed)
// ---------------------------------------------------------------------------
__device__ float g_x[MAXN * H];
__device__ float g_agg[MAXN * H];
__device__ float g_u[MAXN * H];
// Transposed bf16 weights: g_W*[mat][n*128 + k] = bf16(W[mat][k][n]), hi/lo split.
__device__ unsigned short g_Whi[6 * H * H];
__device__ unsigned short g_Wlo[6 * H * H];

// ---------------------------------------------------------------------------
// Prep: W[k][n] -> Wt[n][k], split into bf16 hi + bf16 residual lo.
// ---------------------------------------------------------------------------
__global__ void prep_weights_kernel(const float* __restrict__ W1,
                                    const float* __restrict__ W2)
{
    int i = blockIdx.x * blockDim.x + threadIdx.x;
    if (i >= 6 * H * H) return;
    int mat = i / (H * H);
    int r = i % (H * H);
    int n = r / H;            // output (N) index
    int k = r % H;            // K index
    const float* W = (mat < 3) ? (W1 + (size_t)mat * H * H) : (W2 + (size_t)(mat - 3) * H * H);
    float v = W[k * H + n];
    __nv_bfloat16 hi = __float2bfloat16(v);
    float res = v - __bfloat162float(hi);
    __nv_bfloat16 lo = __float2bfloat16(res);
    g_Whi[i] = __bfloat16_as_ushort(hi);
    g_Wlo[i] = __bfloat16_as_ushort(lo);
}

// ---------------------------------------------------------------------------
// x[i] = emb[z[i]]; also agg[i] = same (init for layer 0)
// ---------------------------------------------------------------------------
__global__ void embed_kernel(const float* __restrict__ emb,
                             const int* __restrict__ z,
                             float* __restrict__ x, float* __restrict__ agg, int N)
{
    int i = blockIdx.x * blockDim.x + threadIdx.x;
    if (i >= N * (H / 4)) return;
    int row = i >> 5;
    int c = i & 31;
    float4 v = ((const float4*)(emb + (size_t)z[row] * H))[c];
    ((float4*)x)[i] = v;
    ((float4*)agg)[i] = v;
}

// ---------------------------------------------------------------------------
// Edge messages: one warp per edge; float4 vector atomics to agg[dst].
// ---------------------------------------------------------------------------
__global__ void edge_kernel(const float* __restrict__ x,
                            float* __restrict__ agg,
                            const int* __restrict__ src,
                            const int* __restrict__ dst,
                            const float* __restrict__ ea,
                            const float* __restrict__ We,
                            const float* __restrict__ be,
                            int E)
{
    const int lane = threadIdx.x & 31;
    const int c = lane * 4;
    const int warp = (blockIdx.x * blockDim.x + threadIdx.x) >> 5;
    const int nwarps = (gridDim.x * blockDim.x) >> 5;

    const float4 w0 = *(const float4*)(We + 0 * H + c);
    const float4 w1 = *(const float4*)(We + 1 * H + c);
    const float4 w2 = *(const float4*)(We + 2 * H + c);
    const float4 w3 = *(const float4*)(We + 3 * H + c);
    const float4 bb = *(const float4*)(be + c);

    for (int e = warp; e < E; e += nwarps) {
        int s = __ldg(src + e);
        int d = __ldg(dst + e);
        float4 a = *(const float4*)(ea + 4 * (size_t)e);

        float4 p;
        p.x = bb.x + a.x * w0.x + a.y * w1.x + a.z * w2.x + a.w * w3.x;
        p.y = bb.y + a.x * w0.y + a.y * w1.y + a.z * w2.y + a.w * w3.y;
        p.z = bb.z + a.x * w0.z + a.y * w1.z + a.z * w2.z + a.w * w3.z;
        p.w = bb.w + a.x * w0.w + a.y * w1.w + a.z * w2.w + a.w * w3.w;

        float4 xv = *(const float4*)(x + (size_t)s * H + c);
        float4 m;
        m.x = fmaxf(xv.x + p.x, 0.0f);
        m.y = fmaxf(xv.y + p.y, 0.0f);
        m.z = fmaxf(xv.z + p.z, 0.0f);
        m.w = fmaxf(xv.w + p.w, 0.0f);

        atomicAdd((float4*)(agg + (size_t)d * H + c), m);
    }
}

// ---------------------------------------------------------------------------
// Tensor-core GEMM via mma.sync (HMMA), split-bf16 fp32 emulation:
//   C[M,128] = act(A[M,128] @ W[128,128] + bias)
//   D = Ahi*Whi + Ahi*Wlo + Alo*Whi, fp32 accumulate.
// CTA: 256 threads / 8 warps, 128-row tile; warp w owns rows w*16..w*16+15.
// A staged fp32 in smem (pad 136), B staged bf16 hi/lo (pad 136).
// ---------------------------------------------------------------------------
#define APAD 136
#define BPAD 136
#define SM_A_FLOATS (128 * APAD)                 // 17408 floats = 69632 B
#define SM_B_SHORTS (128 * BPAD)                 // 17408 ushort = 34816 B
#define GEMM_SMEM (SM_A_FLOATS * 4 + 2 * SM_B_SHORTS * 2)   // 139264 B

__device__ __forceinline__ void mma_bf16(float* c, const uint32_t* a,
                                         uint32_t b0, uint32_t b1)
{
    asm volatile(
        "mma.sync.aligned.m16n8k16.row.col.f32.bf16.bf16.f32 "
        "{%0,%1,%2,%3}, {%4,%5,%6,%7}, {%8,%9}, {%0,%1,%2,%3};"
        : "+f"(c[0]), "+f"(c[1]), "+f"(c[2]), "+f"(c[3])
        : "r"(a[0]), "r"(a[1]), "r"(a[2]), "r"(a[3]), "r"(b0), "r"(b1));
}

__global__ __launch_bounds__(256) void gemm_tc_kernel(
    const float* __restrict__ A, int mat,
    const float* __restrict__ bias,
    float* __restrict__ C1, float* __restrict__ C2,
    int M, int do_silu)
{
    extern __shared__ char smraw[];
    float* As = (float*)smraw;                       // [128][APAD] fp32
    unsigned short* Bhi = (unsigned short*)(smraw + SM_A_FLOATS * 4);
    unsigned short* Blo = Bhi + SM_B_SHORTS;

    const int tid = threadIdx.x;
    const int wid = tid >> 5;
    const int lane = tid & 31;
    const int gid = lane >> 2;       // group id (row within fragment)
    const int tig = lane & 3;        // thread in group (col pairs)
    const int row0 = blockIdx.x * 128;

    // ---- Stage B hi/lo (transposed weights, hot in L2): 2048 uint4 each ----
    {
        const uint4* ghi = (const uint4*)(g_Whi + (size_t)mat * H * H);
        const uint4* glo = (const uint4*)(g_Wlo + (size_t)mat * H * H);
        #pragma unroll
        for (int it = 0; it < 8; it++) {
            int i = tid + it * 256;          // i in [0, 2048)
            int n = i >> 4;                  // 16 uint4 (128 bf16) per row
            int k0 = (i & 15) * 8;
            uint4 vh = ghi[i];
            uint4 vl = glo[i];
            *(uint4*)(Bhi + n * BPAD + k0) = vh;
            *(uint4*)(Blo + n * BPAD + k0) = vl;
        }
    }
    // ---- Stage A tile fp32: 4096 float4 ----
    {
        #pragma unroll
        for (int it = 0; it < 16; it++) {
            int i = tid + it * 256;          // i in [0, 4096)
            int r = i >> 5;                  // 32 float4 per row
            int c0 = (i & 31) * 4;
            int gr = row0 + r;
            float4 v = (gr < M) ? *(const float4*)(A + (size_t)gr * H + c0)
                                : make_float4(0.f, 0.f, 0.f, 0.f);
            *(float4*)(As + r * APAD + c0) = v;
        }
    }
    __syncthreads();

    // ---- Main: warp computes 16 rows x 128 cols ----
    const int rbase = wid * 16;
    float acc[16][4];
    #pragma unroll
    for (int nt = 0; nt < 16; nt++) {
        acc[nt][0] = acc[nt][1] = acc[nt][2] = acc[nt][3] = 0.0f;
    }

    #pragma unroll
    for (int kc = 0; kc < 8; kc++) {
        const int kb = kc * 16 + tig * 2;
        // A fragment: 4 float2 -> bf16 hi/lo
        float2 f0 = *(const float2*)(As + (rbase + gid) * APAD + kb);
        float2 f1 = *(const float2*)(As + (rbase + gid + 8) * APAD + kb);
        float2 f2 = *(const float2*)(As + (rbase + gid) * APAD + kb + 8);
        float2 f3 = *(const float2*)(As + (rbase + gid + 8) * APAD + kb + 8);

        uint32_t ahi[4], alo[4];
        {
            __nv_bfloat162 h0 = __floats2bfloat162_rn(f0.x, f0.y);
            __nv_bfloat162 h1 = __floats2bfloat162_rn(f1.x, f1.y);
            __nv_bfloat162 h2 = __floats2bfloat162_rn(f2.x, f2.y);
            __nv_bfloat162 h3 = __floats2bfloat162_rn(f3.x, f3.y);
            __nv_bfloat162 l0 = __floats2bfloat162_rn(f0.x - __low2float(h0), f0.y - __high2float(h0));
            __nv_bfloat162 l1 = __floats2bfloat162_rn(f1.x - __low2float(h1), f1.y - __high2float(h1));
            __nv_bfloat162 l2 = __floats2bfloat162_rn(f2.x - __low2float(h2), f2.y - __high2float(h2));
            __nv_bfloat162 l3 = __floats2bfloat162_rn(f3.x - __low2float(h3), f3.y - __high2float(h3));
            ahi[0] = *(uint32_t*)&h0; ahi[1] = *(uint32_t*)&h1;
            ahi[2] = *(uint32_t*)&h2; ahi[3] = *(uint32_t*)&h3;
            alo[0] = *(uint32_t*)&l0; alo[1] = *(uint32_t*)&l1;
            alo[2] = *(uint32_t*)&l2; alo[3] = *(uint32_t*)&l3;
        }

        #pragma unroll
        for (int nt = 0; nt < 16; nt++) {
            const int nrow = nt * 8 + gid;
            uint32_t bh0 = *(const uint32_t*)(Bhi + nrow * BPAD + kb);
            uint32_t bh1 = *(const uint32_t*)(Bhi + nrow * BPAD + kb + 8);
            uint32_t bl0 = *(const uint32_t*)(Blo + nrow * BPAD + kb);
            uint32_t bl1 = *(const uint32_t*)(Blo + nrow * BPAD + kb + 8);
            mma_bf16(acc[nt], ahi, bh0, bh1);   // Ahi * Bhi
            mma_bf16(acc[nt], ahi, bl0, bl1);   // Ahi * Blo
            mma_bf16(acc[nt], alo, bh0, bh1);   // Alo * Bhi
        }
    }

    // ---- Epilogue: bias + (silu) + store (dual write optional) ----
    const int rowA = row0 + rbase + gid;
    const int rowB = rowA + 8;
    #pragma unroll
    for (int nt = 0; nt < 16; nt++) {
        const int col = nt * 8 + tig * 2;
        float2 bv = __ldg((const float2*)(bias + col));
        float2 va, vb;
        va.x = acc[nt][0] + bv.x;  va.y = acc[nt][1] + bv.y;
        vb.x = acc[nt][2] + bv.x;  vb.y = acc[nt][3] + bv.y;
        if (do_silu) {
            va.x = va.x / (1.0f + __expf(-va.x));
            va.y = va.y / (1.0f + __expf(-va.y));
            vb.x = vb.x / (1.0f + __expf(-vb.x));
            vb.y = vb.y / (1.0f + __expf(-vb.y));
        }
        if (rowA < M) {
            *(float2*)(C1 + (size_t)rowA * H + col) = va;
            if (C2) *(float2*)(C2 + (size_t)rowA * H + col) = va;
        }
        if (rowB < M) {
            *(float2*)(C1 + (size_t)rowB * H + col) = vb;
            if (C2) *(float2*)(C2 + (size_t)rowB * H + col) = vb;
        }
    }
}

// ---------------------------------------------------------------------------
__global__ void batch_kernel(const int* __restrict__ b, float* __restrict__ o, int N)
{
    int i = blockIdx.x * blockDim.x + threadIdx.x;
    if (i < N) o[i] = (float)b[i];
}

// ---------------------------------------------------------------------------
extern "C" void kernel_launch(void* const* d_in, const int* in_sizes, int n_in,
                              void* d_out, int out_size)
{
    const float* emb = (const float*)d_in[0];
    const float* We  = (const float*)d_in[1];
    const float* be  = (const float*)d_in[2];
    const float* W1  = (const float*)d_in[3];
    const float* b1  = (const float*)d_in[4];
    const float* W2  = (const float*)d_in[5];
    const float* b2  = (const float*)d_in[6];
    const float* ea  = (const float*)d_in[7];
    const int*   z   = (const int*)d_in[8];
    const int*   ei  = (const int*)d_in[9];
    const int*   bat = (const int*)d_in[10];

    const int N = in_sizes[8];
    const int E = in_sizes[9] / 2;
    float* out = (float*)d_out;

    float *x, *agg, *u;
    cudaGetSymbolAddress((void**)&x, g_x);
    cudaGetSymbolAddress((void**)&agg, g_agg);
    cudaGetSymbolAddress((void**)&u, g_u);

    cudaFuncSetAttribute(gemm_tc_kernel, cudaFuncAttributeMaxDynamicSharedMemorySize, GEMM_SMEM);

    prep_weights_kernel<<<(6 * H * H + 255) / 256, 256>>>(W1, W2);
    embed_kernel<<<(N * (H / 4) + 255) / 256, 256>>>(emb, z, x, agg, N);

    const int tiles = (N + 127) / 128;

    for (int l = 0; l < 3; l++) {
        edge_kernel<<<1184, 256>>>(x, agg, ei, ei + E, ea,
                                   We + (size_t)l * 4 * H, be + (size_t)l * H, E);
        // u = silu(agg @ W1 + b1)
        gemm_tc_kernel<<<tiles, 256, GEMM_SMEM>>>(agg, l, b1 + (size_t)l * H, u, nullptr, N, 1);
        // x' = u @ W2 + b2  (dual-write x and agg for next layer)
        if (l == 2) {
            gemm_tc_kernel<<<tiles, 256, GEMM_SMEM>>>(u, 3 + l, b2 + (size_t)l * H, out, nullptr, N, 0);
        } else {
            gemm_tc_kernel<<<tiles, 256, GEMM_SMEM>>>(u, 3 + l, b2 + (size_t)l * H, x, agg, N, 0);
        }
    }

    if ((size_t)out_size >= (size_t)N * H + (size_t)N) {
        batch_kernel<<<(N + 255) / 256, 256>>>(bat, out + (size_t)N * H, N);
    }
}

// round 6
// speedup vs baseline: 1.4251x; 1.2042x over previous
#include <cuda_runtime.h>
#include <cuda_bf16.h>
#include <cstdint>

#define H 128
#define MAXN 100000
#define MAXNP (MAXN + 128)   // pad so unguarded tail-tile loads stay in bounds

// ---------------------------------------------------------------------------
// Scratch (__device__ globals; no allocation allowed)
// ---------------------------------------------------------------------------
__device__ float g_x[MAXNP * H];
__device__ float g_agg[MAXNP * H];
__device__ float g_u[MAXNP * H];
// Transposed bf16 weights: g_W*[mat][n*128 + k] = bf16(W[mat][k][n]), hi/lo split.
__device__ unsigned short g_Whi[6 * H * H];
__device__ unsigned short g_Wlo[6 * H * H];

// ---------------------------------------------------------------------------
// Prep: W[k][n] -> Wt[n][k], split into bf16 hi + bf16 residual lo.
// ---------------------------------------------------------------------------
__global__ void prep_weights_kernel(const float* __restrict__ W1,
                                    const float* __restrict__ W2)
{
    int i = blockIdx.x * blockDim.x + threadIdx.x;
    if (i >= 6 * H * H) return;
    int mat = i / (H * H);
    int r = i % (H * H);
    int n = r / H;
    int k = r % H;
    const float* W = (mat < 3) ? (W1 + (size_t)mat * H * H) : (W2 + (size_t)(mat - 3) * H * H);
    float v = W[k * H + n];
    __nv_bfloat16 hi = __float2bfloat16(v);
    float res = v - __bfloat162float(hi);
    __nv_bfloat16 lo = __float2bfloat16(res);
    g_Whi[i] = __bfloat16_as_ushort(hi);
    g_Wlo[i] = __bfloat16_as_ushort(lo);
}

// ---------------------------------------------------------------------------
// x[i] = emb[z[i]]; also agg[i] = same (init for layer 0)
// ---------------------------------------------------------------------------
__global__ void embed_kernel(const float* __restrict__ emb,
                             const int* __restrict__ z,
                             float* __restrict__ x, float* __restrict__ agg, int N)
{
    int i = blockIdx.x * blockDim.x + threadIdx.x;
    if (i >= N * (H / 4)) return;
    int row = i >> 5;
    int c = i & 31;
    float4 v = ((const float4*)(emb + (size_t)z[row] * H))[c];
    ((float4*)x)[i] = v;
    ((float4*)agg)[i] = v;
}

// ---------------------------------------------------------------------------
// Edge messages: one warp per edge; float4 vector atomics to agg[dst].
// ---------------------------------------------------------------------------
__global__ void edge_kernel(const float* __restrict__ x,
                            float* __restrict__ agg,
                            const int* __restrict__ src,
                            const int* __restrict__ dst,
                            const float* __restrict__ ea,
                            const float* __restrict__ We,
                            const float* __restrict__ be,
                            int E)
{
    const int lane = threadIdx.x & 31;
    const int c = lane * 4;
    const int warp = (blockIdx.x * blockDim.x + threadIdx.x) >> 5;
    const int nwarps = (gridDim.x * blockDim.x) >> 5;

    const float4 w0 = *(const float4*)(We + 0 * H + c);
    const float4 w1 = *(const float4*)(We + 1 * H + c);
    const float4 w2 = *(const float4*)(We + 2 * H + c);
    const float4 w3 = *(const float4*)(We + 3 * H + c);
    const float4 bb = *(const float4*)(be + c);

    for (int e = warp; e < E; e += nwarps) {
        int s = __ldg(src + e);
        int d = __ldg(dst + e);
        float4 a = *(const float4*)(ea + 4 * (size_t)e);

        float4 p;
        p.x = bb.x + a.x * w0.x + a.y * w1.x + a.z * w2.x + a.w * w3.x;
        p.y = bb.y + a.x * w0.y + a.y * w1.y + a.z * w2.y + a.w * w3.y;
        p.z = bb.z + a.x * w0.z + a.y * w1.z + a.z * w2.z + a.w * w3.z;
        p.w = bb.w + a.x * w0.w + a.y * w1.w + a.z * w2.w + a.w * w3.w;

        float4 xv = *(const float4*)(x + (size_t)s * H + c);
        float4 m;
        m.x = fmaxf(xv.x + p.x, 0.0f);
        m.y = fmaxf(xv.y + p.y, 0.0f);
        m.z = fmaxf(xv.z + p.z, 0.0f);
        m.w = fmaxf(xv.w + p.w, 0.0f);

        atomicAdd((float4*)(agg + (size_t)d * H + c), m);
    }
}

// ---------------------------------------------------------------------------
// Tensor-core GEMM via mma.sync, split-bf16 fp32 emulation:
//   C[M,128] = act(A[M,128] @ W[128,128] + bias)
//   D = Ahi*Whi + Ahi*Blo + Alo*Bhi, fp32 accumulate.
// CTA: 256 thr / 8 warps, 128-row tile; warp w owns rows w*16..w*16+15.
// B staged bf16 hi/lo in smem (pad 136). A fragments loaded DIRECTLY from
// gmem (L2-hot) with 1-chunk register prefetch -> smem small enough for
// 2 CTAs/SM, cross-CTA overlap hides staging.
// ---------------------------------------------------------------------------
#define BPAD 136
#define SM_B_SHORTS (128 * BPAD)                 // 17408 ushort = 34816 B
#define GEMM_SMEM (2 * SM_B_SHORTS * 2)          // 69632 B

__device__ __forceinline__ void mma_bf16(float* c, const uint32_t* a,
                                         uint32_t b0, uint32_t b1)
{
    asm volatile(
        "mma.sync.aligned.m16n8k16.row.col.f32.bf16.bf16.f32 "
        "{%0,%1,%2,%3}, {%4,%5,%6,%7}, {%8,%9}, {%0,%1,%2,%3};"
        : "+f"(c[0]), "+f"(c[1]), "+f"(c[2]), "+f"(c[3])
        : "r"(a[0]), "r"(a[1]), "r"(a[2]), "r"(a[3]), "r"(b0), "r"(b1));
}

__global__ __launch_bounds__(256, 2) void gemm_tc_kernel(
    const float* __restrict__ A, int mat,
    const float* __restrict__ bias,
    float* __restrict__ C1, float* __restrict__ C2,
    int M, int do_silu)
{
    extern __shared__ char smraw[];
    unsigned short* Bhi = (unsigned short*)smraw;
    unsigned short* Blo = Bhi + SM_B_SHORTS;

    const int tid = threadIdx.x;
    const int wid = tid >> 5;
    const int lane = tid & 31;
    const int gid = lane >> 2;       // fragment row within 8-group
    const int tig = lane & 3;        // thread-in-group (k pairs)
    const int row0 = blockIdx.x * 128;
    const int rbase = wid * 16;

    // ---- Stage B hi/lo (transposed weights, L2-hot): 2048 uint4 each ----
    {
        const uint4* ghi = (const uint4*)(g_Whi + (size_t)mat * H * H);
        const uint4* glo = (const uint4*)(g_Wlo + (size_t)mat * H * H);
        #pragma unroll
        for (int it = 0; it < 8; it++) {
            int i = tid + it * 256;          // [0, 2048)
            int n = i >> 4;
            int k0 = (i & 15) * 8;
            uint4 vh = ghi[i];
            uint4 vl = glo[i];
            *(uint4*)(Bhi + n * BPAD + k0) = vh;
            *(uint4*)(Blo + n * BPAD + k0) = vl;
        }
    }

    // A fragment gmem pointers (rows rbase+gid and rbase+gid+8; pad rows make
    // unguarded loads safe for the final partial tile).
    const float2* A0 = (const float2*)(A + (size_t)(row0 + rbase + gid) * H) + tig;
    const float2* A1 = A0 + 8 * (H / 2);

    float acc[16][4];
    #pragma unroll
    for (int nt = 0; nt < 16; nt++)
        acc[nt][0] = acc[nt][1] = acc[nt][2] = acc[nt][3] = 0.0f;

    // Prefetch k-chunk 0
    float2 p0 = A0[0], p1 = A1[0], p2 = A0[4], p3 = A1[4];

    __syncthreads();   // B ready

    #pragma unroll
    for (int kc = 0; kc < 8; kc++) {
        float2 f0 = p0, f1 = p1, f2 = p2, f3 = p3;
        if (kc < 7) {
            p0 = A0[(kc + 1) * 8];
            p1 = A1[(kc + 1) * 8];
            p2 = A0[(kc + 1) * 8 + 4];
            p3 = A1[(kc + 1) * 8 + 4];
        }

        uint32_t ahi[4], alo[4];
        {
            __nv_bfloat162 h0 = __floats2bfloat162_rn(f0.x, f0.y);
            __nv_bfloat162 h1 = __floats2bfloat162_rn(f1.x, f1.y);
            __nv_bfloat162 h2 = __floats2bfloat162_rn(f2.x, f2.y);
            __nv_bfloat162 h3 = __floats2bfloat162_rn(f3.x, f3.y);
            __nv_bfloat162 l0 = __floats2bfloat162_rn(f0.x - __low2float(h0), f0.y - __high2float(h0));
            __nv_bfloat162 l1 = __floats2bfloat162_rn(f1.x - __low2float(h1), f1.y - __high2float(h1));
            __nv_bfloat162 l2 = __floats2bfloat162_rn(f2.x - __low2float(h2), f2.y - __high2float(h2));
            __nv_bfloat162 l3 = __floats2bfloat162_rn(f3.x - __low2float(h3), f3.y - __high2float(h3));
            ahi[0] = *(uint32_t*)&h0; ahi[1] = *(uint32_t*)&h1;
            ahi[2] = *(uint32_t*)&h2; ahi[3] = *(uint32_t*)&h3;
            alo[0] = *(uint32_t*)&l0; alo[1] = *(uint32_t*)&l1;
            alo[2] = *(uint32_t*)&l2; alo[3] = *(uint32_t*)&l3;
        }

        const int kb = kc * 16 + tig * 2;
        #pragma unroll
        for (int nt = 0; nt < 16; nt++) {
            const int nrow = nt * 8 + gid;
            uint32_t bh0 = *(const uint32_t*)(Bhi + nrow * BPAD + kb);
            uint32_t bh1 = *(const uint32_t*)(Bhi + nrow * BPAD + kb + 8);
            uint32_t bl0 = *(const uint32_t*)(Blo + nrow * BPAD + kb);
            uint32_t bl1 = *(const uint32_t*)(Blo + nrow * BPAD + kb + 8);
            mma_bf16(acc[nt], ahi, bh0, bh1);   // Ahi * Bhi
            mma_bf16(acc[nt], ahi, bl0, bl1);   // Ahi * Blo
            mma_bf16(acc[nt], alo, bh0, bh1);   // Alo * Bhi
        }
    }

    // ---- Epilogue: bias + (silu) + store (dual write optional) ----
    const int rowA = row0 + rbase + gid;
    const int rowB = rowA + 8;
    #pragma unroll
    for (int nt = 0; nt < 16; nt++) {
        const int col = nt * 8 + tig * 2;
        float2 bv = __ldg((const float2*)(bias + col));
        float2 va, vb;
        va.x = acc[nt][0] + bv.x;  va.y = acc[nt][1] + bv.y;
        vb.x = acc[nt][2] + bv.x;  vb.y = acc[nt][3] + bv.y;
        if (do_silu) {
            va.x = va.x / (1.0f + __expf(-va.x));
            va.y = va.y / (1.0f + __expf(-va.y));
            vb.x = vb.x / (1.0f + __expf(-vb.x));
            vb.y = vb.y / (1.0f + __expf(-vb.y));
        }
        if (rowA < M) {
            *(float2*)(C1 + (size_t)rowA * H + col) = va;
            if (C2) *(float2*)(C2 + (size_t)rowA * H + col) = va;
        }
        if (rowB < M) {
            *(float2*)(C1 + (size_t)rowB * H + col) = vb;
            if (C2) *(float2*)(C2 + (size_t)rowB * H + col) = vb;
        }
    }
}

// ---------------------------------------------------------------------------
__global__ void batch_kernel(const int* __restrict__ b, float* __restrict__ o, int N)
{
    int i = blockIdx.x * blockDim.x + threadIdx.x;
    if (i < N) o[i] = (float)b[i];
}

// ---------------------------------------------------------------------------
extern "C" void kernel_launch(void* const* d_in, const int* in_sizes, int n_in,
                              void* d_out, int out_size)
{
    const float* emb = (const float*)d_in[0];
    const float* We  = (const float*)d_in[1];
    const float* be  = (const float*)d_in[2];
    const float* W1  = (const float*)d_in[3];
    const float* b1  = (const float*)d_in[4];
    const float* W2  = (const float*)d_in[5];
    const float* b2  = (const float*)d_in[6];
    const float* ea  = (const float*)d_in[7];
    const int*   z   = (const int*)d_in[8];
    const int*   ei  = (const int*)d_in[9];
    const int*   bat = (const int*)d_in[10];

    const int N = in_sizes[8];
    const int E = in_sizes[9] / 2;
    float* out = (float*)d_out;

    float *x, *agg, *u;
    cudaGetSymbolAddress((void**)&x, g_x);
    cudaGetSymbolAddress((void**)&agg, g_agg);
    cudaGetSymbolAddress((void**)&u, g_u);

    cudaFuncSetAttribute(gemm_tc_kernel, cudaFuncAttributeMaxDynamicSharedMemorySize, GEMM_SMEM);

    prep_weights_kernel<<<(6 * H * H + 255) / 256, 256>>>(W1, W2);
    embed_kernel<<<(N * (H / 4) + 255) / 256, 256>>>(emb, z, x, agg, N);

    const int tiles = (N + 127) / 128;

    for (int l = 0; l < 3; l++) {
        edge_kernel<<<1184, 256>>>(x, agg, ei, ei + E, ea,
                                   We + (size_t)l * 4 * H, be + (size_t)l * H, E);
        // u = silu(agg @ W1 + b1)
        gemm_tc_kernel<<<tiles, 256, GEMM_SMEM>>>(agg, l, b1 + (size_t)l * H, u, nullptr, N, 1);
        // x' = u @ W2 + b2  (dual-write x and agg for next layer)
        if (l == 2) {
            gemm_tc_kernel<<<tiles, 256, GEMM_SMEM>>>(u, 3 + l, b2 + (size_t)l * H, out, nullptr, N, 0);
        } else {
            gemm_tc_kernel<<<tiles, 256, GEMM_SMEM>>>(u, 3 + l, b2 + (size_t)l * H, x, agg, N, 0);
        }
    }

    if ((size_t)out_size >= (size_t)N * H + (size_t)N) {
        batch_kernel<<<(N + 255) / 256, 256>>>(bat, out + (size_t)N * H, N);
    }
}